// round 7
// baseline (speedup 1.0000x reference)
#include <cuda_runtime.h>
#include <cuda_bf16.h>
#include <stdint.h>
#include <math.h>

// ---------------------------------------------------------------------------
#define CDIM     256
#define MTILE    128
#define NTHREADS 512
#define NQKV     768
#define TOTTOK   131072
#define SA       264          // padded tile stride in halves (528B rows)

// shared memory layout (bytes)
#define S_AH   0                       // A_hi: 128 x SA halves = 67584 B
#define S_AL   (128 * SA * 2)
#define S_B    (2 * 128 * SA * 2)
#define S_BIAS (3 * 128 * SA * 2)      // 1024 floats
#define S_RED  (S_BIAS + 4096)         // 256 floats softmax scratch
#define SMEM_BYTES (S_RED + 1024)      // 207872 B

// ---------------------------------------------------------------------------
__device__ float          g_qkv[(size_t)TOTTOK * NQKV];
__device__ __nv_bfloat16  g_whi[(NQKV + CDIM) * CDIM];
__device__ __nv_bfloat16  g_wlo[(NQKV + CDIM) * CDIM];

// ---------------------------------------------------------------------------
#define MMA16816(c, a, b0, b1) \
    asm volatile("mma.sync.aligned.m16n8k16.row.col.f32.bf16.bf16.f32 " \
        "{%0,%1,%2,%3}, {%4,%5,%6,%7}, {%8,%9}, {%0,%1,%2,%3};" \
        : "+f"((c)[0]), "+f"((c)[1]), "+f"((c)[2]), "+f"((c)[3]) \
        : "r"((a)[0]), "r"((a)[1]), "r"((a)[2]), "r"((a)[3]), \
          "r"(b0), "r"(b1))

#define LDSM4(r, a) \
    asm volatile("ldmatrix.sync.aligned.m8n8.x4.shared.b16 {%0,%1,%2,%3}, [%4];" \
        : "=r"((r)[0]), "=r"((r)[1]), "=r"((r)[2]), "=r"((r)[3]) : "r"(a))

#define SPLIT4(a0,a1,a2,a3,HI0,HI1,LO0,LO1) do { \
    __nv_bfloat16 _h0=__float2bfloat16(a0), _h1=__float2bfloat16(a1); \
    __nv_bfloat16 _h2=__float2bfloat16(a2), _h3=__float2bfloat16(a3); \
    __nv_bfloat16 _l0=__float2bfloat16((a0)-__bfloat162float(_h0)); \
    __nv_bfloat16 _l1=__float2bfloat16((a1)-__bfloat162float(_h1)); \
    __nv_bfloat16 _l2=__float2bfloat16((a2)-__bfloat162float(_h2)); \
    __nv_bfloat16 _l3=__float2bfloat16((a3)-__bfloat162float(_h3)); \
    HI0 = ((uint32_t)__bfloat16_as_ushort(_h1) << 16) | __bfloat16_as_ushort(_h0); \
    HI1 = ((uint32_t)__bfloat16_as_ushort(_h3) << 16) | __bfloat16_as_ushort(_h2); \
    LO0 = ((uint32_t)__bfloat16_as_ushort(_l1) << 16) | __bfloat16_as_ushort(_l0); \
    LO1 = ((uint32_t)__bfloat16_as_ushort(_l3) << 16) | __bfloat16_as_ushort(_l2); \
} while (0)

// ---------------------------------------------------------------------------
__global__ void ga_prep_w(const float* __restrict__ qkv_w,
                          const float* __restrict__ out_w) {
    int i = blockIdx.x * blockDim.x + threadIdx.x;     // < 1024*256
    float v = (i < NQKV * CDIM) ? qkv_w[i] : out_w[i - NQKV * CDIM];
    __nv_bfloat16 h = __float2bfloat16(v);
    g_whi[i] = h;
    g_wlo[i] = __float2bfloat16(v - __bfloat162float(h));
}

// ---------------------------------------------------------------------------
__device__ __forceinline__ void load_b(const __nv_bfloat16* __restrict__ w,
                                       int row_base, __nv_bfloat16* Bs,
                                       int t, int nthr) {
    for (int i = t; i < 4096; i += nthr) {
        int r = i >> 5, q = i & 31;
        uint4 v = __ldg((const uint4*)(w + ((size_t)(row_base + r) << 8)) + q);
        *(uint4*)(Bs + r * SA + q * 8) = v;
    }
}

// 2-term pass: c += Ah*B + Al*B  (B already in Bs)
__device__ __forceinline__ void pass_hilo(const uint32_t aAh[2], const uint32_t aAl[2],
                                          const uint32_t aB[2], float c[2][4][4]) {
    #pragma unroll 4
    for (int k0 = 0; k0 < 256; k0 += 16) {
        uint32_t b0[4], b1[4], ah0[4], ah1[4], al0[4], al1[4];
        LDSM4(b0, aB[0] + k0 * 2);  LDSM4(b1, aB[1] + k0 * 2);
        LDSM4(ah0, aAh[0] + k0 * 2); LDSM4(ah1, aAh[1] + k0 * 2);
        LDSM4(al0, aAl[0] + k0 * 2); LDSM4(al1, aAl[1] + k0 * 2);
        MMA16816(c[0][0], ah0, b0[0], b0[1]); MMA16816(c[0][1], ah0, b0[2], b0[3]);
        MMA16816(c[0][2], ah0, b1[0], b1[1]); MMA16816(c[0][3], ah0, b1[2], b1[3]);
        MMA16816(c[1][0], ah1, b0[0], b0[1]); MMA16816(c[1][1], ah1, b0[2], b0[3]);
        MMA16816(c[1][2], ah1, b1[0], b1[1]); MMA16816(c[1][3], ah1, b1[2], b1[3]);
        MMA16816(c[0][0], al0, b0[0], b0[1]); MMA16816(c[0][1], al0, b0[2], b0[3]);
        MMA16816(c[0][2], al0, b1[0], b1[1]); MMA16816(c[0][3], al0, b1[2], b1[3]);
        MMA16816(c[1][0], al1, b0[0], b0[1]); MMA16816(c[1][1], al1, b0[2], b0[3]);
        MMA16816(c[1][2], al1, b1[0], b1[1]); MMA16816(c[1][3], al1, b1[2], b1[3]);
    }
}

// 1-term pass: c += Ah*B
__device__ __forceinline__ void pass_hi(const uint32_t aAh[2],
                                        const uint32_t aB[2], float c[2][4][4]) {
    #pragma unroll 4
    for (int k0 = 0; k0 < 256; k0 += 16) {
        uint32_t b0[4], b1[4], ah0[4], ah1[4];
        LDSM4(b0, aB[0] + k0 * 2);  LDSM4(b1, aB[1] + k0 * 2);
        LDSM4(ah0, aAh[0] + k0 * 2); LDSM4(ah1, aAh[1] + k0 * 2);
        MMA16816(c[0][0], ah0, b0[0], b0[1]); MMA16816(c[0][1], ah0, b0[2], b0[3]);
        MMA16816(c[0][2], ah0, b1[0], b1[1]); MMA16816(c[0][3], ah0, b1[2], b1[3]);
        MMA16816(c[1][0], ah1, b0[0], b0[1]); MMA16816(c[1][1], ah1, b0[2], b0[3]);
        MMA16816(c[1][2], ah1, b1[0], b1[1]); MMA16816(c[1][3], ah1, b1[2], b1[3]);
    }
}

// ---------------------------------------------------------------------------
__global__ void __launch_bounds__(NTHREADS, 1)
ga_main(const float* __restrict__ x,
        const float* __restrict__ qkv_b,
        const float* __restrict__ out_b,
        const float* __restrict__ ln_g,
        const float* __restrict__ ln_b,
        float* __restrict__ out)
{
    extern __shared__ char smem[];
    __nv_bfloat16* Ah    = (__nv_bfloat16*)(smem + S_AH);
    __nv_bfloat16* Al    = (__nv_bfloat16*)(smem + S_AL);
    __nv_bfloat16* Bs    = (__nv_bfloat16*)(smem + S_B);
    float*         s_bias= (float*)(smem + S_BIAS);
    float*         s_red = (float*)(smem + S_RED);

    const int tid  = threadIdx.x;
    const int wid  = tid >> 5;
    const int lane = tid & 31;
    const int warp_m = wid & 3;          // 4 x M32
    const int warp_n = wid >> 2;         // 4 x N32
    const int tok0 = blockIdx.x * MTILE;

    // ldmatrix lane addresses (conflict-free with SA=264)
    uint32_t aAh[2], aAl[2], aB[2];
    {
        const int arow = warp_m * 32 + (lane & 15);
        const int akoff = (lane >> 4) << 3;
        aAh[0] = (uint32_t)__cvta_generic_to_shared(Ah + arow * SA + akoff);
        aAh[1] = aAh[0] + 16 * SA * 2;
        aAl[0] = (uint32_t)__cvta_generic_to_shared(Al + arow * SA + akoff);
        aAl[1] = aAl[0] + 16 * SA * 2;
        const int brow = (lane & 7) + ((lane >> 4) << 3);
        const int bkoff = ((lane >> 3) & 1) << 3;
        aB[0] = (uint32_t)__cvta_generic_to_shared(Bs + (warp_n * 32 + brow) * SA + bkoff);
        aB[1] = aB[0] + 16 * SA * 2;
    }

    for (int i = tid; i < 1024; i += NTHREADS)
        s_bias[i] = (i < NQKV) ? __ldg(qkv_b + i) : __ldg(out_b + i - NQKV);

    // ---- Phase A: threads 0-127 LN + split -> Ah/Al; rest preload B chunk 0
    if (tid < 128) {
        const float* xr = x + ((size_t)(tok0 + tid) << 8);
        float s = 0.f, s2 = 0.f;
        #pragma unroll 8
        for (int j = 0; j < 64; j++) {
            float4 v = __ldg((const float4*)xr + j);
            s  += v.x + v.y + v.z + v.w;
            s2 += v.x * v.x + v.y * v.y + v.z * v.z + v.w * v.w;
        }
        const float mean = s * (1.f / 256.f);
        const float rstd = rsqrtf(s2 * (1.f / 256.f) - mean * mean + 1e-5f);
        __nv_bfloat16* ah = Ah + tid * SA;
        __nv_bfloat16* al = Al + tid * SA;
        #pragma unroll 4
        for (int j = 0; j < 64; j++) {
            const int k = j * 4;
            float4 v  = __ldg((const float4*)xr + j);
            float4 g4 = __ldg((const float4*)(ln_g + k));
            float4 b4 = __ldg((const float4*)(ln_b + k));
            float a0 = (v.x - mean) * rstd * g4.x + b4.x;
            float a1 = (v.y - mean) * rstd * g4.y + b4.y;
            float a2 = (v.z - mean) * rstd * g4.z + b4.z;
            float a3 = (v.w - mean) * rstd * g4.w + b4.w;
            uint32_t h0, h1, l0, l1;
            SPLIT4(a0, a1, a2, a3, h0, h1, l0, l1);
            *(uint2*)(ah + k) = make_uint2(h0, h1);
            *(uint2*)(al + k) = make_uint2(l0, l1);
        }
    } else {
        load_b(g_whi, 0, Bs, tid - 128, NTHREADS - 128);
    }
    __syncthreads();

    // ---- Phase B: QKV projection, 6 N-chunks of 128
    for (int nc = 0; nc < 6; nc++) {
        float c[2][4][4];
        #pragma unroll
        for (int m = 0; m < 2; m++)
            #pragma unroll
            for (int j = 0; j < 4; j++)
                #pragma unroll
                for (int q = 0; q < 4; q++) c[m][j][q] = 0.f;

        pass_hilo(aAh, aAl, aB, c);          // (Ah+Al) * Whi
        __syncthreads();
        load_b(g_wlo, nc * 128, Bs, tid, NTHREADS);
        __syncthreads();
        pass_hi(aAh, aB, c);                 // Ah * Wlo
        __syncthreads();
        if (nc < 5) load_b(g_whi, (nc + 1) * 128, Bs, tid, NTHREADS);

        // epilogue -> g_qkv (fp32, +bias)
        {
            float* base = g_qkv + (size_t)(tok0 + warp_m * 32 + (lane >> 2)) * NQKV
                        + nc * 128 + warp_n * 32 + (lane & 3) * 2;
            const float* bb = s_bias + nc * 128 + warp_n * 32 + (lane & 3) * 2;
            #pragma unroll
            for (int m = 0; m < 2; m++) {
                #pragma unroll
                for (int j = 0; j < 4; j++) {
                    float b0 = bb[j * 8], b1 = bb[j * 8 + 1];
                    float* p = base + (size_t)m * 16 * NQKV + j * 8;
                    *(float2*)p = make_float2(c[m][j][0] + b0, c[m][j][1] + b1);
                    *(float2*)(p + (size_t)8 * NQKV) =
                        make_float2(c[m][j][2] + b0, c[m][j][3] + b1);
                }
            }
        }
        __syncthreads();
    }

    // ---- Phase C: attention (fp32), writes o split directly into Ah/Al
    {
        const float SCALE = 0.08838834764831845f;  // 128^-0.5
        #pragma unroll 1
        for (int pp = 0; pp < 4; pp++) {
            const int p = wid + pp * 16;           // 0..63 (group,head) pairs
            const int g = p >> 1, h = p & 1;
            const float* qb = g_qkv + (size_t)(tok0 + g * 4) * NQKV + h * 128;
            const float* kb = qb + 256;
            const float* vb = qb + 512;

            const int pid = lane >> 1, si = pid >> 2, sj = pid & 3, half = lane & 1;
            const float4* q4 = (const float4*)(qb + si * NQKV + half * 64);
            const float4* k4 = (const float4*)(kb + sj * NQKV + half * 64);
            float partial = 0.f;
            #pragma unroll
            for (int d = 0; d < 16; d++) {
                float4 a = __ldg(q4 + d), b = __ldg(k4 + d);
                partial += a.x * b.x + a.y * b.y + a.z * b.z + a.w * b.w;
            }
            partial += __shfl_xor_sync(0xffffffffu, partial, 1);
            const float sc = partial * SCALE;
            float mx = sc;
            mx = fmaxf(mx, __shfl_xor_sync(0xffffffffu, mx, 2));
            mx = fmaxf(mx, __shfl_xor_sync(0xffffffffu, mx, 4));
            float e = __expf(sc - mx);
            float ssum = e;
            ssum += __shfl_xor_sync(0xffffffffu, ssum, 2);
            ssum += __shfl_xor_sync(0xffffffffu, ssum, 4);
            const float P = e / ssum;
            if (half == 0) s_red[wid * 16 + pid] = P;
            __syncwarp();

            const int d0 = lane * 4;
            float4 vv[4];
            #pragma unroll
            for (int j2 = 0; j2 < 4; j2++)
                vv[j2] = __ldg((const float4*)(vb + j2 * NQKV + d0));
            #pragma unroll
            for (int i2 = 0; i2 < 4; i2++) {
                float4 o4 = make_float4(0.f, 0.f, 0.f, 0.f);
                #pragma unroll
                for (int j2 = 0; j2 < 4; j2++) {
                    const float pij = s_red[wid * 16 + i2 * 4 + j2];
                    o4.x += pij * vv[j2].x; o4.y += pij * vv[j2].y;
                    o4.z += pij * vv[j2].z; o4.w += pij * vv[j2].w;
                }
                uint32_t h0, h1, l0, l1;
                SPLIT4(o4.x, o4.y, o4.z, o4.w, h0, h1, l0, l1);
                const int off = (g * 4 + i2) * SA + h * 128 + d0;
                *(uint2*)(Ah + off) = make_uint2(h0, h1);
                *(uint2*)(Al + off) = make_uint2(l0, l1);
            }
            __syncwarp();
        }
    }
    __syncthreads();

    // ---- Phase E: out projection, 2 N-chunks, +bias +residual
    load_b(g_whi, NQKV, Bs, tid, NTHREADS);
    __syncthreads();
    for (int nc = 0; nc < 2; nc++) {
        float c[2][4][4];
        #pragma unroll
        for (int m = 0; m < 2; m++)
            #pragma unroll
            for (int j = 0; j < 4; j++)
                #pragma unroll
                for (int q = 0; q < 4; q++) c[m][j][q] = 0.f;

        pass_hilo(aAh, aAl, aB, c);
        __syncthreads();
        load_b(g_wlo, NQKV + nc * 128, Bs, tid, NTHREADS);
        __syncthreads();
        pass_hi(aAh, aB, c);
        __syncthreads();
        if (nc == 0) load_b(g_whi, NQKV + 128, Bs, tid, NTHREADS);

        {
            const int col0 = nc * 128 + warp_n * 32 + (lane & 3) * 2;
            const float* bb = s_bias + NQKV + col0;
            #pragma unroll
            for (int m = 0; m < 2; m++) {
                const int row = tok0 + warp_m * 32 + m * 16 + (lane >> 2);
                #pragma unroll
                for (int j = 0; j < 4; j++) {
                    float b0 = bb[j * 8], b1 = bb[j * 8 + 1];
                    size_t gi = (size_t)row * CDIM + col0 + j * 8;
                    float2 x0 = __ldg((const float2*)(x + gi));
                    float2 x1 = __ldg((const float2*)(x + gi + (size_t)8 * CDIM));
                    *(float2*)(out + gi) =
                        make_float2(c[m][j][0] + b0 + x0.x, c[m][j][1] + b1 + x0.y);
                    *(float2*)(out + gi + (size_t)8 * CDIM) =
                        make_float2(c[m][j][2] + b0 + x1.x, c[m][j][3] + b1 + x1.y);
                }
            }
        }
        __syncthreads();
    }
}

// ---------------------------------------------------------------------------
extern "C" void kernel_launch(void* const* d_in, const int* in_sizes, int n_in,
                              void* d_out, int out_size)
{
    const float* x     = (const float*)d_in[0];
    const float* qkv_w = (const float*)d_in[1];
    const float* qkv_b = (const float*)d_in[2];
    const float* out_w = (const float*)d_in[3];
    const float* out_b = (const float*)d_in[4];
    const float* ln_g  = (const float*)d_in[5];
    const float* ln_b  = (const float*)d_in[6];
    float* out = (float*)d_out;

    const int ntok = in_sizes[0] / CDIM;     // 131072
    const int nblk = ntok / MTILE;           // 1024

    ga_prep_w<<<(NQKV + CDIM) * CDIM / 256, 256>>>(qkv_w, out_w);

    cudaFuncSetAttribute(ga_main,
                         cudaFuncAttributeMaxDynamicSharedMemorySize, SMEM_BYTES);
    ga_main<<<nblk, NTHREADS, SMEM_BYTES>>>(x, qkv_b, out_b, ln_g, ln_b, out);
}

// round 8
// speedup vs baseline: 1.5699x; 1.5699x over previous
#include <cuda_runtime.h>
#include <cuda_bf16.h>
#include <stdint.h>
#include <math.h>

// ---------------------------------------------------------------------------
#define CDIM     256
#define MTILE    128
#define NTHREADS 256
#define NQKV     768
#define TOTTOK   131072
#define SA       264          // A tile stride in halves (528B rows; LDSM conflict-free)

#define NSTAGE      4
#define SB_ROW      144       // B stage row stride bytes (9x16B -> conflict-free)
#define STAGE_BYTES (128 * SB_ROW)   // 18432

// shared memory layout (bytes)
#define S_AH   0                          // 128 x SA halves = 67584
#define S_AL   67584
#define S_BST  135168                     // 4 stages x 18432 = 73728
#define S_BIAS 208896                     // 1024 floats
#define S_RED  212992                     // softmax scratch
#define SMEM_BYTES 214016

// ---------------------------------------------------------------------------
__device__ float          g_qkv[(size_t)TOTTOK * NQKV];
__device__ __nv_bfloat16  g_whi[(NQKV + CDIM) * CDIM];
__device__ __nv_bfloat16  g_wlo[(NQKV + CDIM) * CDIM];

// ---------------------------------------------------------------------------
#define MMA16816(c, a, b0, b1) \
    asm volatile("mma.sync.aligned.m16n8k16.row.col.f32.bf16.bf16.f32 " \
        "{%0,%1,%2,%3}, {%4,%5,%6,%7}, {%8,%9}, {%0,%1,%2,%3};" \
        : "+f"((c)[0]), "+f"((c)[1]), "+f"((c)[2]), "+f"((c)[3]) \
        : "r"((a)[0]), "r"((a)[1]), "r"((a)[2]), "r"((a)[3]), \
          "r"(b0), "r"(b1))

#define LDSM4(r, a) \
    asm volatile("ldmatrix.sync.aligned.m8n8.x4.shared.b16 {%0,%1,%2,%3}, [%4];" \
        : "=r"((r)[0]), "=r"((r)[1]), "=r"((r)[2]), "=r"((r)[3]) : "r"(a))

#define CP_ASYNC16(dst, src) \
    asm volatile("cp.async.cg.shared.global [%0], [%1], 16;" \
        :: "r"(dst), "l"(src) : "memory")
#define CP_COMMIT() asm volatile("cp.async.commit_group;" ::: "memory")
#define CP_WAIT(n)  asm volatile("cp.async.wait_group %0;" :: "n"(n) : "memory")

#define SPLIT4(a0,a1,a2,a3,HI0,HI1,LO0,LO1) do { \
    __nv_bfloat16 _h0=__float2bfloat16(a0), _h1=__float2bfloat16(a1); \
    __nv_bfloat16 _h2=__float2bfloat16(a2), _h3=__float2bfloat16(a3); \
    __nv_bfloat16 _l0=__float2bfloat16((a0)-__bfloat162float(_h0)); \
    __nv_bfloat16 _l1=__float2bfloat16((a1)-__bfloat162float(_h1)); \
    __nv_bfloat16 _l2=__float2bfloat16((a2)-__bfloat162float(_h2)); \
    __nv_bfloat16 _l3=__float2bfloat16((a3)-__bfloat162float(_h3)); \
    HI0 = ((uint32_t)__bfloat16_as_ushort(_h1) << 16) | __bfloat16_as_ushort(_h0); \
    HI1 = ((uint32_t)__bfloat16_as_ushort(_h3) << 16) | __bfloat16_as_ushort(_h2); \
    LO0 = ((uint32_t)__bfloat16_as_ushort(_l1) << 16) | __bfloat16_as_ushort(_l0); \
    LO1 = ((uint32_t)__bfloat16_as_ushort(_l3) << 16) | __bfloat16_as_ushort(_l2); \
} while (0)

// ---------------------------------------------------------------------------
__global__ void ga_prep_w(const float* __restrict__ qkv_w,
                          const float* __restrict__ out_w) {
    int i = blockIdx.x * blockDim.x + threadIdx.x;     // < 1024*256
    float v = (i < NQKV * CDIM) ? qkv_w[i] : out_w[i - NQKV * CDIM];
    __nv_bfloat16 h = __float2bfloat16(v);
    g_whi[i] = h;
    g_wlo[i] = __float2bfloat16(v - __bfloat162float(h));
}

// ---------------------------------------------------------------------------
// stream stage s (64 total): s<48 -> QKV chunk s>>3; s>=48 -> out chunk (s-48)>>3.
// half = (s>>2)&1 (0: g_whi, 1: g_wlo), kc = s&3 (64-halves k-chunk).
__device__ __forceinline__ void issue_stage(int s, uint32_t sbst, int tid) {
    if (s < 64) {
        const int half = (s >> 2) & 1;
        const int kc   = s & 3;
        const int row0 = (s < 48) ? (s >> 3) * 128 : NQKV + ((s - 48) >> 3) * 128;
        const __nv_bfloat16* w = (half ? g_wlo : g_whi)
                               + ((size_t)row0 << 8) + kc * 64;
        const uint32_t dst0 = sbst + (uint32_t)(s & 3) * STAGE_BYTES;
        #pragma unroll
        for (int k = 0; k < 4; k++) {
            const int i  = tid + k * NTHREADS;
            const int r  = i >> 3, cq = i & 7;
            CP_ASYNC16(dst0 + r * SB_ROW + cq * 16,
                       (const void*)(w + ((size_t)r << 8) + cq * 8));
        }
    }
    CP_COMMIT();
}

// ---------------------------------------------------------------------------
__global__ void __launch_bounds__(NTHREADS, 1)
ga_main(const float* __restrict__ x,
        const float* __restrict__ qkv_b,
        const float* __restrict__ out_b,
        const float* __restrict__ ln_g,
        const float* __restrict__ ln_b,
        float* __restrict__ out)
{
    extern __shared__ char smem[];
    __nv_bfloat16* Ah    = (__nv_bfloat16*)(smem + S_AH);
    __nv_bfloat16* Al    = (__nv_bfloat16*)(smem + S_AL);
    float*         s_bias= (float*)(smem + S_BIAS);
    float*         s_red = (float*)(smem + S_RED);

    const int tid  = threadIdx.x;
    const int wid  = tid >> 5;
    const int lane = tid & 31;
    const int warp_m = wid & 1;          // 2 x M64
    const int warp_n = wid >> 1;         // 4 x N32
    const int tok0 = blockIdx.x * MTILE;

    const uint32_t sbst = (uint32_t)__cvta_generic_to_shared(smem + S_BST);

    // LDSM lane addresses
    uint32_t aAh0, aAl0, boff0;
    {
        const int arow  = warp_m * 64 + (lane & 15);
        const int akoff = (lane >> 4) << 3;                 // halves
        aAh0 = (uint32_t)__cvta_generic_to_shared(Ah + arow * SA + akoff);
        aAl0 = (uint32_t)__cvta_generic_to_shared(Al + arow * SA + akoff);
        const int brow  = (lane & 7) + ((lane >> 4) << 3);
        const int bkoff = ((lane >> 3) & 1) << 3;           // halves
        boff0 = (uint32_t)((warp_n * 32 + brow) * SB_ROW + bkoff * 2);
    }

    // prologue: prefetch stages 0..2 (overlaps LN below)
    issue_stage(0, sbst, tid);
    issue_stage(1, sbst, tid);
    issue_stage(2, sbst, tid);

    for (int i = tid; i < 1024; i += NTHREADS)
        s_bias[i] = (i < NQKV) ? __ldg(qkv_b + i) : __ldg(out_b + i - NQKV);

    // ---- Phase A: LN + bf16 split -> Ah/Al (threads 0-127, one token each)
    if (tid < 128) {
        const float* xr = x + ((size_t)(tok0 + tid) << 8);
        float s = 0.f, s2 = 0.f;
        #pragma unroll 8
        for (int j = 0; j < 64; j++) {
            float4 v = __ldg((const float4*)xr + j);
            s  += v.x + v.y + v.z + v.w;
            s2 += v.x * v.x + v.y * v.y + v.z * v.z + v.w * v.w;
        }
        const float mean = s * (1.f / 256.f);
        const float rstd = rsqrtf(s2 * (1.f / 256.f) - mean * mean + 1e-5f);
        __nv_bfloat16* ah = Ah + tid * SA;
        __nv_bfloat16* al = Al + tid * SA;
        #pragma unroll 4
        for (int j = 0; j < 64; j++) {
            const int k = j * 4;
            float4 v  = __ldg((const float4*)xr + j);
            float4 g4 = __ldg((const float4*)(ln_g + k));
            float4 b4 = __ldg((const float4*)(ln_b + k));
            float a0 = (v.x - mean) * rstd * g4.x + b4.x;
            float a1 = (v.y - mean) * rstd * g4.y + b4.y;
            float a2 = (v.z - mean) * rstd * g4.z + b4.z;
            float a3 = (v.w - mean) * rstd * g4.w + b4.w;
            uint32_t h0, h1, l0, l1;
            SPLIT4(a0, a1, a2, a3, h0, h1, l0, l1);
            *(uint2*)(ah + k) = make_uint2(h0, h1);
            *(uint2*)(al + k) = make_uint2(l0, l1);
        }
    }
    __syncthreads();

    float c[4][4][4];

    // ---- Phase B: QKV projection (stream stages 0..47)
    for (int s = 0; s < 48; s++) {
        if ((s & 7) == 0) {
            #pragma unroll
            for (int mt = 0; mt < 4; mt++)
                #pragma unroll
                for (int jt = 0; jt < 4; jt++)
                    #pragma unroll
                    for (int q = 0; q < 4; q++) c[mt][jt][q] = 0.f;
        }
        CP_WAIT(2);
        __syncthreads();
        const int kc = s & 3;
        const uint32_t aB0 = sbst + (uint32_t)(s & 3) * STAGE_BYTES + boff0;
        const uint32_t aB1 = aB0 + 16 * SB_ROW;
        const int lo_half = (s >> 2) & 1;
        #pragma unroll
        for (int ks = 0; ks < 4; ks++) {
            const uint32_t ab = (uint32_t)(kc * 128 + ks * 32);
            uint32_t b0[4], b1[4];
            LDSM4(b0, aB0 + ks * 32); LDSM4(b1, aB1 + ks * 32);
            uint32_t ah[4][4];
            #pragma unroll
            for (int mt = 0; mt < 4; mt++) LDSM4(ah[mt], aAh0 + mt * (16*SA*2) + ab);
            #pragma unroll
            for (int mt = 0; mt < 4; mt++) {
                MMA16816(c[mt][0], ah[mt], b0[0], b0[1]);
                MMA16816(c[mt][1], ah[mt], b0[2], b0[3]);
                MMA16816(c[mt][2], ah[mt], b1[0], b1[1]);
                MMA16816(c[mt][3], ah[mt], b1[2], b1[3]);
            }
            if (!lo_half) {           // merged second term: Al * Whi
                uint32_t al[4][4];
                #pragma unroll
                for (int mt = 0; mt < 4; mt++) LDSM4(al[mt], aAl0 + mt * (16*SA*2) + ab);
                #pragma unroll
                for (int mt = 0; mt < 4; mt++) {
                    MMA16816(c[mt][0], al[mt], b0[0], b0[1]);
                    MMA16816(c[mt][1], al[mt], b0[2], b0[3]);
                    MMA16816(c[mt][2], al[mt], b1[0], b1[1]);
                    MMA16816(c[mt][3], al[mt], b1[2], b1[3]);
                }
            }
        }
        __syncthreads();
        issue_stage(s + 3, sbst, tid);

        if ((s & 7) == 7) {           // epilogue chunk -> g_qkv (fp32, +bias)
            const int nc = s >> 3;
            float* base = g_qkv + (size_t)(tok0 + warp_m * 64 + (lane >> 2)) * NQKV
                        + nc * 128 + warp_n * 32 + (lane & 3) * 2;
            const float* bb = s_bias + nc * 128 + warp_n * 32 + (lane & 3) * 2;
            #pragma unroll
            for (int mt = 0; mt < 4; mt++) {
                #pragma unroll
                for (int jt = 0; jt < 4; jt++) {
                    float b0v = bb[jt * 8], b1v = bb[jt * 8 + 1];
                    float* p = base + (size_t)mt * 16 * NQKV + jt * 8;
                    *(float2*)p = make_float2(c[mt][jt][0] + b0v, c[mt][jt][1] + b1v);
                    *(float2*)(p + (size_t)8 * NQKV) =
                        make_float2(c[mt][jt][2] + b0v, c[mt][jt][3] + b1v);
                }
            }
        }
    }
    __syncthreads();

    // ---- Phase C: attention (fp32), writes o split into Ah/Al
    {
        const float SCALE = 0.08838834764831845f;  // 128^-0.5
        #pragma unroll 1
        for (int pp = 0; pp < 8; pp++) {
            const int p = wid + pp * 8;            // 0..63 (group,head) pairs
            const int g = p >> 1, h = p & 1;
            const float* qb = g_qkv + (size_t)(tok0 + g * 4) * NQKV + h * 128;
            const float* kb = qb + 256;
            const float* vb = qb + 512;

            const int pid = lane >> 1, si = pid >> 2, sj = pid & 3, half = lane & 1;
            const float4* q4 = (const float4*)(qb + si * NQKV + half * 64);
            const float4* k4 = (const float4*)(kb + sj * NQKV + half * 64);
            float partial = 0.f;
            #pragma unroll
            for (int d = 0; d < 16; d++) {
                float4 a = __ldg(q4 + d), b = __ldg(k4 + d);
                partial += a.x * b.x + a.y * b.y + a.z * b.z + a.w * b.w;
            }
            partial += __shfl_xor_sync(0xffffffffu, partial, 1);
            const float sc = partial * SCALE;
            float mx = sc;
            mx = fmaxf(mx, __shfl_xor_sync(0xffffffffu, mx, 2));
            mx = fmaxf(mx, __shfl_xor_sync(0xffffffffu, mx, 4));
            float e = __expf(sc - mx);
            float ssum = e;
            ssum += __shfl_xor_sync(0xffffffffu, ssum, 2);
            ssum += __shfl_xor_sync(0xffffffffu, ssum, 4);
            const float P = e / ssum;
            if (half == 0) s_red[wid * 16 + pid] = P;
            __syncwarp();

            const int d0 = lane * 4;
            float4 vv[4];
            #pragma unroll
            for (int j2 = 0; j2 < 4; j2++)
                vv[j2] = __ldg((const float4*)(vb + j2 * NQKV + d0));
            #pragma unroll
            for (int i2 = 0; i2 < 4; i2++) {
                float4 o4 = make_float4(0.f, 0.f, 0.f, 0.f);
                #pragma unroll
                for (int j2 = 0; j2 < 4; j2++) {
                    const float pij = s_red[wid * 16 + i2 * 4 + j2];
                    o4.x += pij * vv[j2].x; o4.y += pij * vv[j2].y;
                    o4.z += pij * vv[j2].z; o4.w += pij * vv[j2].w;
                }
                uint32_t h0, h1, l0, l1;
                SPLIT4(o4.x, o4.y, o4.z, o4.w, h0, h1, l0, l1);
                const int off = (g * 4 + i2) * SA + h * 128 + d0;
                *(uint2*)(Ah + off) = make_uint2(h0, h1);
                *(uint2*)(Al + off) = make_uint2(l0, l1);
            }
            __syncwarp();
        }
    }
    __syncthreads();

    // ---- Phase E: out projection (stream stages 48..63), +bias +residual
    for (int s = 48; s < 64; s++) {
        if ((s & 7) == 0) {
            #pragma unroll
            for (int mt = 0; mt < 4; mt++)
                #pragma unroll
                for (int jt = 0; jt < 4; jt++)
                    #pragma unroll
                    for (int q = 0; q < 4; q++) c[mt][jt][q] = 0.f;
        }
        CP_WAIT(2);
        __syncthreads();
        const int kc = s & 3;
        const uint32_t aB0 = sbst + (uint32_t)(s & 3) * STAGE_BYTES + boff0;
        const uint32_t aB1 = aB0 + 16 * SB_ROW;
        const int lo_half = (s >> 2) & 1;
        #pragma unroll
        for (int ks = 0; ks < 4; ks++) {
            const uint32_t ab = (uint32_t)(kc * 128 + ks * 32);
            uint32_t b0[4], b1[4];
            LDSM4(b0, aB0 + ks * 32); LDSM4(b1, aB1 + ks * 32);
            uint32_t ah[4][4];
            #pragma unroll
            for (int mt = 0; mt < 4; mt++) LDSM4(ah[mt], aAh0 + mt * (16*SA*2) + ab);
            #pragma unroll
            for (int mt = 0; mt < 4; mt++) {
                MMA16816(c[mt][0], ah[mt], b0[0], b0[1]);
                MMA16816(c[mt][1], ah[mt], b0[2], b0[3]);
                MMA16816(c[mt][2], ah[mt], b1[0], b1[1]);
                MMA16816(c[mt][3], ah[mt], b1[2], b1[3]);
            }
            if (!lo_half) {
                uint32_t al[4][4];
                #pragma unroll
                for (int mt = 0; mt < 4; mt++) LDSM4(al[mt], aAl0 + mt * (16*SA*2) + ab);
                #pragma unroll
                for (int mt = 0; mt < 4; mt++) {
                    MMA16816(c[mt][0], al[mt], b0[0], b0[1]);
                    MMA16816(c[mt][1], al[mt], b0[2], b0[3]);
                    MMA16816(c[mt][2], al[mt], b1[0], b1[1]);
                    MMA16816(c[mt][3], al[mt], b1[2], b1[3]);
                }
            }
        }
        __syncthreads();
        issue_stage(s + 3, sbst, tid);

        if ((s & 7) == 7) {          // epilogue: +bias +residual -> out
            const int nc = (s - 48) >> 3;
            const int col0 = nc * 128 + warp_n * 32 + (lane & 3) * 2;
            const float* bb = s_bias + NQKV + col0;
            #pragma unroll
            for (int mt = 0; mt < 4; mt++) {
                const int row = tok0 + warp_m * 64 + mt * 16 + (lane >> 2);
                #pragma unroll
                for (int jt = 0; jt < 4; jt++) {
                    float b0v = bb[jt * 8], b1v = bb[jt * 8 + 1];
                    size_t gi = (size_t)row * CDIM + col0 + jt * 8;
                    float2 x0 = __ldg((const float2*)(x + gi));
                    float2 x1 = __ldg((const float2*)(x + gi + (size_t)8 * CDIM));
                    *(float2*)(out + gi) =
                        make_float2(c[mt][jt][0] + b0v + x0.x, c[mt][jt][1] + b1v + x0.y);
                    *(float2*)(out + gi + (size_t)8 * CDIM) =
                        make_float2(c[mt][jt][2] + b0v + x1.x, c[mt][jt][3] + b1v + x1.y);
                }
            }
        }
    }
}

// ---------------------------------------------------------------------------
extern "C" void kernel_launch(void* const* d_in, const int* in_sizes, int n_in,
                              void* d_out, int out_size)
{
    const float* x     = (const float*)d_in[0];
    const float* qkv_w = (const float*)d_in[1];
    const float* qkv_b = (const float*)d_in[2];
    const float* out_w = (const float*)d_in[3];
    const float* out_b = (const float*)d_in[4];
    const float* ln_g  = (const float*)d_in[5];
    const float* ln_b  = (const float*)d_in[6];
    float* out = (float*)d_out;

    const int ntok = in_sizes[0] / CDIM;     // 131072
    const int nblk = ntok / MTILE;           // 1024

    ga_prep_w<<<(NQKV + CDIM) * CDIM / 256, 256>>>(qkv_w, out_w);

    cudaFuncSetAttribute(ga_main,
                         cudaFuncAttributeMaxDynamicSharedMemorySize, SMEM_BYTES);
    ga_main<<<nblk, NTHREADS, SMEM_BYTES>>>(x, qkv_b, out_b, ln_g, ln_b, out);
}